// round 9
// baseline (speedup 1.0000x reference)
#include <cuda_runtime.h>
#include <cstdint>

// ----------------------------------------------------------------------------
// LightOnOCRPatchMerger, round 8: tf32 mma.sync + FFMA warp-specialized hybrid.
//   out[11955,1024] = merged[11955,4096] @ W[1024,4096]^T   (K sub-major)
// Legacy mma.sync tf32 saturates the pair-shared tensor unit (~512 MACs/cyc/
// SM-pair = measured 703us ceiling). Add the idle per-SM FMA pipe: tile
// 128x160 = 128 tensor cols (8 warps) + 32 FFMA cols (4 warps, 1/SMSP,
// 8x4 thread tile, exact fp32). Per-chunk both sides take 2048 pair-cycles.
// N = 6 hybrid tiles + one 64-wide tensor-only remainder (templated).
// Operands pre-marshaled (chunk-major, k-interleaved, XOR-swizzled) so each
// stage is two cp.async.bulk ops into a 3-deep mbarrier ring.
// ----------------------------------------------------------------------------

#define M_TOTAL 11955
#define M_PAD   12032          // 94 tiles of 128
#define NCHUNK  128            // K=4096 / 32
#define A_BYTES 16384          // 128 rows * 128B
#define STRIDE  36864          // stage stride (A 16K + B up to 20K)
#define NSTAGE  3
#define SMEM_DYN (NSTAGE * STRIDE)   // 110592

// [chunk][row][granule] 16B granules. Row's 32 k-values: tig=k&3, j=k>>2,
// h=j>>2, slot=j&3; storage granule P = (2*tig+h) ^ (row&7); float slot=slot.
// One 16B granule holds k = {tig+16h+0, +4, +8, +12}.
__device__ float4 gA[(size_t)NCHUNK * M_PAD * 8];   // 197 MB
__device__ float4 gB[(size_t)NCHUNK * 1024 * 8];    // 16 MB

__device__ __forceinline__ float rna_tf32(float x) {
    unsigned u; asm("cvt.rna.tf32.f32 %0, %1;" : "=r"(u) : "f"(x));
    return __uint_as_float(u);
}

__device__ __forceinline__ int tok_of(int m, int sub) {
    const int boff[6] = {0, 2420, 4620, 6060, 9085, 10525};
    const int toff[6] = {0, 9680, 18480, 24240, 36340, 42100};
    const int gw[6]   = {88, 110, 90, 110, 64, 110};
    const int nbw[6]  = {44, 55, 45, 55, 32, 55};
    int img = 0;
    #pragma unroll
    for (int i = 1; i < 6; i++) if (m >= boff[i]) img = i;
    int local = m - boff[img];
    int bh = local / nbw[img], bw = local - bh * nbw[img];
    int w = gw[img];
    return toff[img] + 2 * bh * w + 2 * bw + (sub >> 1) * w + (sub & 1);
}

__global__ void prep_A(const float* __restrict__ F) {
    int idx = blockIdx.x * 256 + threadIdx.x;   // m*8 + gidx
    int c = blockIdx.y;
    int m = idx >> 3, gidx = idx & 7;
    int mc = m < M_TOTAL ? m : M_TOTAL - 1;
    int pos = gidx ^ (m & 7);
    int tig = pos >> 1, h = pos & 1;
    int sub = c >> 5;
    int dbase = (c & 31) * 32 + tig + 16 * h;
    const float* src = F + (size_t)tok_of(mc, sub) * 1024 + dbase;
    float4 v;
    v.x = rna_tf32(src[0]);  v.y = rna_tf32(src[4]);
    v.z = rna_tf32(src[8]);  v.w = rna_tf32(src[12]);
    gA[((size_t)c * M_PAD + m) * 8 + gidx] = v;
}

__global__ void prep_B(const float* __restrict__ W) {
    int idx = blockIdx.x * 256 + threadIdx.x;   // n*8 + gidx
    int c = blockIdx.y;
    int n = idx >> 3, gidx = idx & 7;
    int pos = gidx ^ (n & 7);
    int tig = pos >> 1, h = pos & 1;
    int sub = c >> 5;
    int kbase = (c & 31) * 32 + tig + 16 * h;   // d; W col = d*4 + sub
    const float* src = W + (size_t)n * 4096 + sub;
    float4 v;
    v.x = rna_tf32(src[(kbase + 0) * 4]);
    v.y = rna_tf32(src[(kbase + 4) * 4]);
    v.z = rna_tf32(src[(kbase + 8) * 4]);
    v.w = rna_tf32(src[(kbase + 12) * 4]);
    gB[((size_t)c * 1024 + n) * 8 + gidx] = v;
}

__device__ __forceinline__ void mma_tf32(float* d, const unsigned* a, const unsigned* b) {
    asm volatile(
        "mma.sync.aligned.m16n8k8.row.col.f32.tf32.tf32.f32 "
        "{%0,%1,%2,%3}, {%4,%5,%6,%7}, {%8,%9}, {%0,%1,%2,%3};"
        : "+f"(d[0]), "+f"(d[1]), "+f"(d[2]), "+f"(d[3])
        : "r"(a[0]), "r"(a[1]), "r"(a[2]), "r"(a[3]), "r"(b[0]), "r"(b[1]));
}

#define WAITP(a, ph) \
    asm volatile("{\n\t.reg .pred P;\n\tWL%=:\n\t" \
        "mbarrier.try_wait.parity.acquire.cta.shared::cta.b64 P, [%0], %1, 0x989680;\n\t" \
        "@P bra.uni WD%=;\n\tbra.uni WL%=;\n\tWD%=:\n\t}" :: "r"(a), "r"(ph) : "memory")

#define LDS128F(v, addr) \
    asm volatile("ld.shared.v4.f32 {%0,%1,%2,%3},[%4];" \
        : "=f"((v).x), "=f"((v).y), "=f"((v).z), "=f"((v).w) : "r"(addr))

template<bool WIDE>
__device__ __forceinline__ void run_tile(float* __restrict__ out,
                                         unsigned sbase, unsigned mb,
                                         int nt, int mt) {
    constexpr int NC = WIDE ? 8 : 4;              // tensor col-frags per warp
    constexpr int CW = WIDE ? 64 : 32;            // tensor cols per N-warp
    constexpr unsigned BB = WIDE ? 20480u : 8192u; // B bytes per stage

    const int tid = threadIdx.x, lane = tid & 31, w = tid >> 5;
    const int wm = w >> 1, wn = w & 1, g = lane >> 2, tig = lane & 3;
    const int fw = w - 8, tr = lane >> 3, tc = lane & 7;

    const char* srcA0 = (const char*)gA + (size_t)mt * A_BYTES;
    const char* srcB0 = (const char*)gB + (size_t)nt * (160 * 128);

    auto issue = [&](int chunk, int slot) {
        unsigned bar = mb + slot * 8;
        asm volatile("mbarrier.arrive.expect_tx.shared.b64 _, [%0], %1;"
                     :: "r"(bar), "r"(A_BYTES + BB) : "memory");
        unsigned da = sbase + slot * STRIDE;
        const char* sa = srcA0 + (size_t)chunk * (M_PAD * 128);
        const char* sb = srcB0 + (size_t)chunk * (1024 * 128);
        asm volatile("cp.async.bulk.shared::cluster.global.mbarrier::complete_tx::bytes "
                     "[%0], [%1], %2, [%3];"
                     :: "r"(da), "l"(sa), "r"((unsigned)A_BYTES), "r"(bar) : "memory");
        asm volatile("cp.async.bulk.shared::cluster.global.mbarrier::complete_tx::bytes "
                     "[%0], [%1], %2, [%3];"
                     :: "r"(da + A_BYTES), "l"(sb), "r"(BB), "r"(bar) : "memory");
    };
    if (tid == 0) { issue(0, 0); issue(1, 1); issue(2, 2); }

    float acc[2][NC][4] = {};        // tensor accumulators
    float facc[8][4] = {};           // FFMA accumulators
    const unsigned rowA0 = (unsigned)(wm * 32 + g) * 128;
    const unsigned rowB0 = (unsigned)(wn * CW + g) * 128;

    int s = 0, p = 0;
    #pragma unroll 1
    for (int it = 0; it < NCHUNK; it++) {
        WAITP(mb + s * 8, p);
        unsigned sA = sbase + s * STRIDE;
        unsigned sB = sA + A_BYTES;
        if (w < 8) {
            // ---------------- tensor warps ----------------
            #pragma unroll
            for (int ks = 0; ks < 4; ks++) {
                unsigned go = ((((unsigned)(2 * tig + (ks >> 1))) ^ (unsigned)g) << 4)
                            + ((ks & 1) << 3);
                unsigned a[2][4];
                #pragma unroll
                for (int f = 0; f < 2; f++) {
                    unsigned ad = sA + rowA0 + f * (16 * 128) + go;
                    asm volatile("ld.shared.v2.b32 {%0,%1},[%2];"
                                 : "=r"(a[f][0]), "=r"(a[f][2]) : "r"(ad));
                    asm volatile("ld.shared.v2.b32 {%0,%1},[%2];"
                                 : "=r"(a[f][1]), "=r"(a[f][3]) : "r"(ad + 8 * 128));
                }
                #pragma unroll
                for (int c = 0; c < NC; c++) {
                    unsigned bd = sB + rowB0 + c * (8 * 128) + go;
                    unsigned b[2];
                    asm volatile("ld.shared.v2.b32 {%0,%1},[%2];"
                                 : "=r"(b[0]), "=r"(b[1]) : "r"(bd));
                    mma_tf32(acc[0][c], a[0], b);
                    mma_tf32(acc[1][c], a[1], b);
                }
            }
        } else if (WIDE) {
            // ---------------- FFMA warps (1/SMSP), cols 128..159 ----------
            unsigned aB = sA + (unsigned)(fw * 32 + tr * 8) * 128;
            unsigned bB = sB + (unsigned)(128 + tc * 4) * 128;
            #pragma unroll
            for (int gi = 0; gi < 8; gi++) {
                float4 Ar[8];
                #pragma unroll
                for (int i = 0; i < 8; i++) {       // tr-staggered: no conflicts
                    int rr = (i + tr * 2) & 7;
                    LDS128F(Ar[rr], aB + rr * 128 + ((gi ^ rr) << 4));
                }
                float4 Br[4];
                #pragma unroll
                for (int j = 0; j < 4; j++) {       // tc-staggered
                    int jj = (j + tc) & 3;
                    int nn = tc * 4 + jj;
                    LDS128F(Br[jj], bB + jj * 128 + ((gi ^ (nn & 7)) << 4));
                }
                #pragma unroll
                for (int i = 0; i < 8; i++)
                    #pragma unroll
                    for (int j = 0; j < 4; j++) {
                        float f = facc[i][j];
                        f = fmaf(Ar[i].x, Br[j].x, f);
                        f = fmaf(Ar[i].y, Br[j].y, f);
                        f = fmaf(Ar[i].z, Br[j].z, f);
                        f = fmaf(Ar[i].w, Br[j].w, f);
                        facc[i][j] = f;
                    }
            }
        }
        __syncthreads();
        if (tid == 0 && it + NSTAGE < NCHUNK) issue(it + NSTAGE, s);
        if (++s == NSTAGE) { s = 0; p ^= 1; }
    }

    // ---------------- epilogues ----------------
    if (w < 8) {
        #pragma unroll
        for (int f = 0; f < 2; f++)
            #pragma unroll
            for (int hh = 0; hh < 2; hh++) {
                int m = mt * 128 + wm * 32 + f * 16 + g + hh * 8;
                if (m < M_TOTAL) {
                    #pragma unroll
                    for (int c = 0; c < NC; c++) {
                        int n = nt * 160 + wn * CW + c * 8 + tig * 2;
                        float2 v = make_float2(acc[f][c][hh * 2], acc[f][c][hh * 2 + 1]);
                        *reinterpret_cast<float2*>(out + (size_t)m * 1024 + n) = v;
                    }
                }
            }
    } else if (WIDE) {
        int n0 = nt * 160 + 128 + tc * 4;
        #pragma unroll
        for (int i = 0; i < 8; i++) {
            int m = mt * 128 + fw * 32 + tr * 8 + i;
            if (m < M_TOTAL) {
                float4 v = make_float4(facc[i][0], facc[i][1], facc[i][2], facc[i][3]);
                *reinterpret_cast<float4*>(out + (size_t)m * 1024 + n0) = v;
            }
        }
    }
}

__global__ void __launch_bounds__(384, 1)
merger_hybrid(float* __restrict__ out) {
    extern __shared__ float4 stg[];
    __shared__ uint64_t mbar[NSTAGE];
    unsigned sbase, mb;
    asm("{ .reg .u64 t; cvta.to.shared.u64 t, %1; cvt.u32.u64 %0, t; }"
        : "=r"(sbase) : "l"((void*)stg));
    asm("{ .reg .u64 t; cvta.to.shared.u64 t, %1; cvt.u32.u64 %0, t; }"
        : "=r"(mb) : "l"((void*)mbar));

    if (threadIdx.x == 0) {
        #pragma unroll
        for (int s = 0; s < NSTAGE; s++)
            asm volatile("mbarrier.init.shared.b64 [%0], 1;"
                         :: "r"(mb + s * 8) : "memory");
    }
    asm volatile("fence.proxy.async;" ::: "memory");
    __syncthreads();

    const int nt = blockIdx.x, mt = blockIdx.y;
    if (nt < 6) run_tile<true>(out, sbase, mb, nt, mt);   // hybrid 160-wide
    else        run_tile<false>(out, sbase, mb, nt, mt);  // tensor-only 64-wide
}

extern "C" void kernel_launch(void* const* d_in, const int* in_sizes, int n_in,
                              void* d_out, int out_size) {
    const float* feat = (const float*)d_in[0];   // [47820, 1024] fp32
    const float* W    = (const float*)d_in[1];   // [1024, 4096] fp32
    float* out = (float*)d_out;                  // [11955, 1024] fp32

    prep_B<<<dim3(32, 128), 256>>>(W);
    prep_A<<<dim3(376, 128), 256>>>(feat);

    cudaFuncSetAttribute(merger_hybrid,
                         cudaFuncAttributeMaxDynamicSharedMemorySize, SMEM_DYN);
    merger_hybrid<<<dim3(7, 94), 384, SMEM_DYN>>>(out);
}